// round 12
// baseline (speedup 1.0000x reference)
#include <cuda_runtime.h>
#include <cuda_fp16.h>
#include <cstdint>
#include <cstddef>

// Problem constants
#define BB 4
#define SS 4096
#define DD 1024
#define HH 16
#define DK 64
#define MM (BB * SS)          // 16384

// ---------------- scratch (device globals; no runtime allocation) ----------
__device__ __half g_a16[(size_t)MM * DD];
__device__ __half g_qo16[(size_t)MM * DD];   // projected Q (phi), fp16
__device__ __half g_ko16[(size_t)MM * DD];   // projected K (phi), fp16
__device__ __half g_vo16[(size_t)MM * DD];   // projected V, fp16

__device__ __half g_wq16[(size_t)DD * DD];
__device__ __half g_wk16[(size_t)DD * DD];
__device__ __half g_wv16[(size_t)DD * DD];
__device__ __half g_wo16[(size_t)DD * DD];

#define KV_SPLIT 16
__device__ float g_KVp[(size_t)KV_SPLIT * 64 * DK * DK];
__device__ float g_KSp[(size_t)KV_SPLIT * 64 * DK];
__device__ float g_KV[(size_t)64 * DK * DK];
__device__ float g_KS[(size_t)64 * DK];

// ============================ PTX helpers ==================================
__device__ __forceinline__ uint32_t s2u(const void* p) {
    uint32_t a;
    asm("{ .reg .u64 t; cvta.to.shared.u64 t, %1; cvt.u32.u64 %0, t; }"
        : "=r"(a) : "l"(p));
    return a;
}

__device__ __forceinline__ void cp16(uint32_t dst, const void* src) {
    asm volatile("cp.async.cg.shared.global [%0], [%1], 16;"
                 :: "r"(dst), "l"(src) : "memory");
}

#define LDSM4(r, addr)                                                         \
    asm volatile("ldmatrix.sync.aligned.m8n8.x4.shared.b16 "                   \
                 "{%0,%1,%2,%3}, [%4];"                                        \
                 : "=r"((r)[0]), "=r"((r)[1]), "=r"((r)[2]), "=r"((r)[3])      \
                 : "r"(addr))

#define MMA16816(d, a, b)                                                      \
    asm volatile("mma.sync.aligned.m16n8k16.row.col.f32.f16.f16.f32 "          \
                 "{%0,%1,%2,%3}, {%4,%5,%6,%7}, {%8,%9}, {%0,%1,%2,%3};"       \
                 : "+f"((d)[0]), "+f"((d)[1]), "+f"((d)[2]), "+f"((d)[3])      \
                 : "r"((a)[0]), "r"((a)[1]), "r"((a)[2]), "r"((a)[3]),         \
                   "r"((b)[0]), "r"((b)[1]))

// ============================ weight conversion ============================
struct ConvArgs {
    const float* src[4];
    __half* dst[4];
    int n4;                // float4 units per tensor (all equal)
};

__global__ void __launch_bounds__(256)
conv_w(ConvArgs a)
{
    const int u = blockIdx.x * blockDim.x + threadIdx.x;
    const int t = u / a.n4;
    if (t >= 4) return;
    const int i = u - t * a.n4;
    float4 v = ((const float4*)a.src[t])[i];
    __half2* yp = (__half2*)a.dst[t];
    yp[2 * i]     = __floats2half2_rn(v.x, v.y);
    yp[2 * i + 1] = __floats2half2_rn(v.z, v.w);
}

// ============================ mma.sync GEMM ================================
// C[m,n] = sum_k A[m,k]*W[n,k], fp32 accumulate.
// A source: fp32 (A32 set; converted in-kernel) or fp16 (A16).
// mode: 0 plain->f32, 1 phi->f32, 2 +bias->f32, 3 phi->f16, 4 plain->f16
#define TM 128
#define TN 128
#define BKE 64                      // k elems per stage
#define KCH (DD / BKE)              // 16 chunks
#define RS 144                      // smem row stride bytes (128 data + 16 pad)
#define SPLIT_B (128 * RS)          // 18432
#define STAGE_B (2 * SPLIT_B)       // 36864 (A, W)
#define NST 3
#define GSMEM (NST * STAGE_B)       // 110592 -> 2 CTAs/SM (221KB)

struct GemmArgs {
    const float* A32[3];            // fp32 activation source (or null)
    const __half* A16[3];           // fp16 A source (used if A32 null)
    const __half* B[3];
    const float* bias[3];
    void* C[3];
    int mode[3];
};

__global__ void __launch_bounds__(256, 2)
gemm_mma(GemmArgs p)
{
    extern __shared__ char smem[];
    const uint32_t sb = s2u(smem);
    const int tid = threadIdx.x;
    const int lane = tid & 31;
    const int warp = tid >> 5;
    const int wm = warp & 3;        // 32-row slab
    const int wn = warp >> 2;       // 64-col slab
    const int z = blockIdx.z;
    const int bm = blockIdx.y * TM;
    const int bn = blockIdx.x * TN;
    const int mode = p.mode[z];
    const bool a32 = (p.A32[z] != nullptr);

    const float*  pA32 = a32 ? (p.A32[z] + (size_t)bm * DD) : nullptr;
    const __half* pA16 = a32 ? nullptr : (p.A16[z] + (size_t)bm * DD);
    const __half* pW   = p.B[z] + (size_t)bn * DD;

    // cp.async producer: W always; A too when fp16 source.
    auto produce = [&](int c) {
        const uint32_t st = sb + (uint32_t)(c % NST) * STAGE_B;
        if (!a32) {
#pragma unroll
            for (int it = 0; it < 4; it++) {
                const int idx = it * 256 + tid;     // 0..1023
                const int r = idx >> 3, seg = idx & 7;
                cp16(st + (uint32_t)(r * RS + seg * 16),
                     pA16 + (size_t)r * DD + c * BKE + seg * 8);
            }
        }
#pragma unroll
        for (int it = 0; it < 4; it++) {
            const int idx = it * 256 + tid;
            const int r = idx >> 3, seg = idx & 7;
            cp16(st + (uint32_t)(SPLIT_B + r * RS + seg * 16),
                 pW + (size_t)r * DD + c * BKE + seg * 8);
        }
        asm volatile("cp.async.commit_group;" ::: "memory");
    };

    // fp32-A load/convert/store helpers (group g covers 256 of 1024 16B units)
    auto lda = [&](int c, int g, float4* rr) {
        const int idx = g * 256 + tid;
        const int r = idx >> 3, seg = idx & 7;
        const float* src = pA32 + (size_t)r * DD + c * BKE + seg * 8;
        rr[0] = ((const float4*)src)[0];
        rr[1] = ((const float4*)src)[1];
    };
    auto sta = [&](int c, int g, const float4* rr) {
        const int idx = g * 256 + tid;
        const int r = idx >> 3, seg = idx & 7;
        __half2 h0 = __floats2half2_rn(rr[0].x, rr[0].y);
        __half2 h1 = __floats2half2_rn(rr[0].z, rr[0].w);
        __half2 h2 = __floats2half2_rn(rr[1].x, rr[1].y);
        __half2 h3 = __floats2half2_rn(rr[1].z, rr[1].w);
        uint4 u;
        u.x = *(uint32_t*)&h0; u.y = *(uint32_t*)&h1;
        u.z = *(uint32_t*)&h2; u.w = *(uint32_t*)&h3;
        *(uint4*)(smem + (size_t)((c % NST) * STAGE_B + r * RS + seg * 16)) = u;
    };
    auto fillA = [&](int c) {
#pragma unroll
        for (int g = 0; g < 4; g++) {
            float4 rr[2];
            lda(c, g, rr);
            sta(c, g, rr);
        }
    };

    float acc[2][8][4];
#pragma unroll
    for (int i = 0; i < 2; i++)
#pragma unroll
        for (int j = 0; j < 8; j++)
#pragma unroll
            for (int k = 0; k < 4; k++) acc[i][j][k] = 0.0f;

    if (a32) { fillA(0); fillA(1); }
    produce(0);
    produce(1);

    for (int c = 0; c < KCH; c++) {
        if (c == KCH - 1)
            asm volatile("cp.async.wait_group 0;" ::: "memory");
        else
            asm volatile("cp.async.wait_group 1;" ::: "memory");
        __syncthreads();
        const bool pre = (c + 2 < KCH);
        if (pre) produce(c + 2);

        const uint32_t st = sb + (uint32_t)(c % NST) * STAGE_B;
        float4 ar[2][2];
#pragma unroll
        for (int step = 0; step < 4; step++) {
            uint32_t ah[2][4], bh[8][2];
#pragma unroll
            for (int mt = 0; mt < 2; mt++) {
                const int row = wm * 32 + mt * 16 + (lane & 15);
                const uint32_t off =
                    (uint32_t)(row * RS + step * 32 + ((lane >> 4) & 1) * 16);
                LDSM4(ah[mt], st + off);
            }
#pragma unroll
            for (int nt2 = 0; nt2 < 4; nt2++) {
                const int nrow = wn * 64 + nt2 * 16 + (lane & 7) + ((lane >> 4) & 1) * 8;
                const uint32_t off =
                    (uint32_t)(nrow * RS + step * 32 + ((lane >> 3) & 1) * 16);
                uint32_t r[4];
                LDSM4(r, st + SPLIT_B + off);
                bh[nt2 * 2][0] = r[0]; bh[nt2 * 2][1] = r[1];
                bh[nt2 * 2 + 1][0] = r[2]; bh[nt2 * 2 + 1][1] = r[3];
            }
            if (a32 && pre) lda(c + 2, step, ar[step & 1]);
#pragma unroll
            for (int mt = 0; mt < 2; mt++)
#pragma unroll
                for (int nt = 0; nt < 8; nt++)
                    MMA16816(acc[mt][nt], ah[mt], bh[nt]);
            if (a32 && pre && step >= 1) sta(c + 2, step - 1, ar[(step - 1) & 1]);
        }
        if (a32 && pre) sta(c + 2, 3, ar[1]);
    }

    // epilogue
    const int gr = lane >> 2;        // 0..7
    const int gc = (lane & 3) * 2;   // 0,2,4,6
#pragma unroll
    for (int mt = 0; mt < 2; mt++) {
#pragma unroll
        for (int nt = 0; nt < 8; nt++) {
            const int row0 = bm + wm * 32 + mt * 16 + gr;
            const int col  = bn + wn * 64 + nt * 8 + gc;
            float v[4] = {acc[mt][nt][0], acc[mt][nt][1],
                          acc[mt][nt][2], acc[mt][nt][3]};
            if (mode == 1 || mode == 3) {
#pragma unroll
                for (int j = 0; j < 4; j++)
                    v[j] = (v[j] > 0.0f) ? (v[j] + 1.0f) : expf(v[j]);
            } else if (mode == 2) {
                const float b0 = p.bias[z][col], b1 = p.bias[z][col + 1];
                v[0] += b0; v[1] += b1; v[2] += b0; v[3] += b1;
            }
            if (mode <= 2) {
                float* C = (float*)p.C[z];
                float2 p0; p0.x = v[0]; p0.y = v[1];
                float2 p1; p1.x = v[2]; p1.y = v[3];
                *(float2*)(C + (size_t)row0 * DD + col) = p0;
                *(float2*)(C + (size_t)(row0 + 8) * DD + col) = p1;
            } else {
                __half* C = (__half*)p.C[z];
                *(__half2*)(C + (size_t)row0 * DD + col) =
                    __floats2half2_rn(v[0], v[1]);
                *(__half2*)(C + (size_t)(row0 + 8) * DD + col) =
                    __floats2half2_rn(v[2], v[3]);
            }
        }
    }
}

// ---------------- KV accumulation: KV[bh] = sum_s k(s) outer v(s) ----------
__global__ void __launch_bounds__(256)
kv_kernel(const __half* __restrict__ Kp, const __half* __restrict__ Vp,
          float* __restrict__ KVp, float* __restrict__ KSp)
{
    const int bh = blockIdx.x;          // 0..63
    const int sp = blockIdx.y;          // 0..KV_SPLIT-1
    const int b = bh >> 4, h = bh & 15;
    const int tid = threadIdx.x;
    const int tx = tid & 15;
    const int ty = tid >> 4;

    __shared__ float ks[8][68];
    __shared__ float vs[8][68];

    float acc[4][4];
#pragma unroll
    for (int i = 0; i < 4; i++)
#pragma unroll
        for (int j = 0; j < 4; j++) acc[i][j] = 0.0f;
    float kacc = 0.0f;

    const int sPer = SS / KV_SPLIT;     // 256
    const int sBase = sp * sPer;

    const int lrow = (tid >> 3) & 7;    // 0..7
    const int lseg = tid & 7;           // 0..7 (8 halves each)

    for (int s0 = 0; s0 < sPer; s0 += 8) {
        if (tid < 128) {
            const __half* src = (tid < 64) ? Kp : Vp;
            const size_t gaddr =
                ((size_t)(b * SS + sBase + s0 + lrow)) * DD + h * DK + lseg * 8;
            uint4 raw = *(const uint4*)(src + gaddr);
            const __half2* hp = (const __half2*)&raw;
            float2 f0 = __half22float2(hp[0]);
            float2 f1 = __half22float2(hp[1]);
            float2 f2 = __half22float2(hp[2]);
            float2 f3 = __half22float2(hp[3]);
            float* dst = (tid < 64) ? &ks[lrow][lseg * 8] : &vs[lrow][lseg * 8];
            float4 o0; o0.x = f0.x; o0.y = f0.y; o0.z = f1.x; o0.w = f1.y;
            float4 o1; o1.x = f2.x; o1.y = f2.y; o1.z = f3.x; o1.w = f3.y;
            *(float4*)(dst)     = o0;
            *(float4*)(dst + 4) = o1;
        }
        __syncthreads();

        if (tid < 64) {
#pragma unroll
            for (int j = 0; j < 8; j++) kacc += ks[j][tid];
        }
#pragma unroll
        for (int j = 0; j < 8; j++) {
            float4 av = *(const float4*)&ks[j][ty * 4];
            float4 bv = *(const float4*)&vs[j][tx * 4];
            float a[4] = {av.x, av.y, av.z, av.w};
            float c[4] = {bv.x, bv.y, bv.z, bv.w};
#pragma unroll
            for (int i = 0; i < 4; i++)
#pragma unroll
                for (int jj = 0; jj < 4; jj++)
                    acc[i][jj] += a[i] * c[jj];
        }
        __syncthreads();
    }

    float* outp = KVp + ((size_t)(sp * 64 + bh)) * (DK * DK);
#pragma unroll
    for (int i = 0; i < 4; i++)
#pragma unroll
        for (int jj = 0; jj < 4; jj++)
            outp[(ty * 4 + i) * DK + tx * 4 + jj] = acc[i][jj];

    if (tid < 64)
        KSp[((size_t)(sp * 64 + bh)) * DK + tid] = kacc;
}

// ---------------- parallel reduce of KV partials ---------------------------
__global__ void __launch_bounds__(256)
kv_reduce(const float* __restrict__ KVp, const float* __restrict__ KSp,
          float* __restrict__ KV, float* __restrict__ KS)
{
    const int bh = blockIdx.x;
    const int part = blockIdx.y;        // 0..3
    const int tid = threadIdx.x;
    const int e4 = part * 256 + tid;    // float4 index 0..1023

    const float4* src = (const float4*)KVp;
    float4 s; s.x = 0.f; s.y = 0.f; s.z = 0.f; s.w = 0.f;
#pragma unroll
    for (int r = 0; r < KV_SPLIT; r++) {
        float4 v = src[((size_t)(r * 64 + bh)) * (DK * DK / 4) + e4];
        s.x += v.x; s.y += v.y; s.z += v.z; s.w += v.w;
    }
    ((float4*)KV)[(size_t)bh * (DK * DK / 4) + e4] = s;

    if (part == 0 && tid < DK) {
        float t = 0.0f;
#pragma unroll
        for (int r = 0; r < KV_SPLIT; r++)
            t += KSp[((size_t)(r * 64 + bh)) * DK + tid];
        KS[(size_t)bh * DK + tid] = t;
    }
}

// ---------------- attention normalize: fp16 Q -> fp16 output ---------------
__global__ void __launch_bounds__(256)
attn_kernel(const __half* __restrict__ Q16, const float* __restrict__ KV,
            const float* __restrict__ KS, __half* __restrict__ A16)
{
    const int bh = blockIdx.x;          // 0..63
    const int sc = blockIdx.y;          // 0..7 (512 rows per block)
    const int b = bh >> 4, h = bh & 15;
    const int tid = threadIdx.x;
    const int w = tid >> 5, l = tid & 31;

    __shared__ float KVs[DK * DK];
    __shared__ float KSs[DK];
    __shared__ float qb[8][8][64];      // [warp][row][dk]

    for (int i = tid; i < (DK * DK) / 4; i += 256)
        ((float4*)KVs)[i] = ((const float4*)(KV + (size_t)bh * DK * DK))[i];
    if (tid < DK) KSs[tid] = KS[(size_t)bh * DK + tid];
    __syncthreads();

    const size_t qbase = ((size_t)(b * SS) + sc * 512 + w * 64) * DD + h * DK;

    for (int g = 0; g < 8; g++) {
        const __half* qrow = Q16 + qbase + (size_t)(g * 8) * DD;
#pragma unroll
        for (int t = 0; t < 2; t++) {
            const int idx = l + t * 32;           // 0..63
            const int r = idx >> 3, seg = idx & 7;
            uint4 raw = *(const uint4*)(qrow + (size_t)r * DD + seg * 8);
            const __half2* hp = (const __half2*)&raw;
            float2 f0 = __half22float2(hp[0]);
            float2 f1 = __half22float2(hp[1]);
            float2 f2 = __half22float2(hp[2]);
            float2 f3 = __half22float2(hp[3]);
            float* dst = &qb[w][r][seg * 8];
            float4 o0; o0.x = f0.x; o0.y = f0.y; o0.z = f1.x; o0.w = f1.y;
            float4 o1; o1.x = f2.x; o1.y = f2.y; o1.z = f3.x; o1.w = f3.y;
            *(float4*)(dst)     = o0;
            *(float4*)(dst + 4) = o1;
        }
        __syncwarp();

        float n0[8], n1[8], dn[8];
#pragma unroll
        for (int r = 0; r < 8; r++) { n0[r] = 0.f; n1[r] = 0.f; dn[r] = 0.f; }
#pragma unroll
        for (int dk = 0; dk < DK; dk++) {
            const float kv0 = KVs[dk * DK + l];
            const float kv1 = KVs[dk * DK + l + 32];
            const float ksv = KSs[dk];
#pragma unroll
            for (int r = 0; r < 8; r++) {
                const float q = qb[w][r][dk];
                n0[r] += q * kv0;
                n1[r] += q * kv1;
                dn[r] += q * ksv;
            }
        }
#pragma unroll
        for (int r = 0; r < 8; r++) {
            const size_t orow = qbase + (size_t)(g * 8 + r) * DD;
            const float inv = 1.0f / (dn[r] + 1e-6f);
            A16[orow + l]      = __float2half_rn(n0[r] * inv);
            A16[orow + l + 32] = __float2half_rn(n1[r] * inv);
        }
        __syncwarp();
    }
}

// ---------------- launch ---------------------------------------------------
extern "C" void kernel_launch(void* const* d_in, const int* in_sizes, int n_in,
                              void* d_out, int out_size)
{
    const float* query = (const float*)d_in[0];
    const float* key   = (const float*)d_in[1];
    const float* value = (const float*)d_in[2];
    const float* Wq    = (const float*)d_in[3];
    const float* Wk    = (const float*)d_in[4];
    const float* Wv    = (const float*)d_in[5];
    const float* Wo    = (const float*)d_in[6];
    const float* bo    = (const float*)d_in[7];
    float* out = (float*)d_out;

    float *gKVp, *gKSp, *gKV, *gKS;
    __half *a16, *qo16, *ko16, *vo16;
    __half *wq16, *wk16, *wv16, *wo16;
    cudaGetSymbolAddress((void**)&gKVp, g_KVp);
    cudaGetSymbolAddress((void**)&gKSp, g_KSp);
    cudaGetSymbolAddress((void**)&gKV, g_KV);
    cudaGetSymbolAddress((void**)&gKS, g_KS);
    cudaGetSymbolAddress((void**)&a16, g_a16);
    cudaGetSymbolAddress((void**)&qo16, g_qo16);
    cudaGetSymbolAddress((void**)&ko16, g_ko16);
    cudaGetSymbolAddress((void**)&vo16, g_vo16);
    cudaGetSymbolAddress((void**)&wq16, g_wq16);
    cudaGetSymbolAddress((void**)&wk16, g_wk16);
    cudaGetSymbolAddress((void**)&wv16, g_wv16);
    cudaGetSymbolAddress((void**)&wo16, g_wo16);

    cudaFuncSetAttribute(gemm_mma, cudaFuncAttributeMaxDynamicSharedMemorySize,
                         GSMEM);

    // weight conversion only (activations converted inside the QKV GEMM)
    const int nW4 = (DD * DD) / 4;     // 262144
    ConvArgs ca;
    ca.src[0] = Wq; ca.dst[0] = wq16;
    ca.src[1] = Wk; ca.dst[1] = wk16;
    ca.src[2] = Wv; ca.dst[2] = wv16;
    ca.src[3] = Wo; ca.dst[3] = wo16;
    ca.n4 = nW4;
    conv_w<<<(4 * nW4 + 255) / 256, 256>>>(ca);

    // fused Q/K/V projections; fp32 A converted in-kernel; fp16 outputs
    GemmArgs aq;
    aq.A32[0] = query; aq.A16[0] = nullptr; aq.B[0] = wq16;
    aq.C[0] = qo16; aq.bias[0] = bo; aq.mode[0] = 3;
    aq.A32[1] = key;   aq.A16[1] = nullptr; aq.B[1] = wk16;
    aq.C[1] = ko16; aq.bias[1] = bo; aq.mode[1] = 3;
    aq.A32[2] = value; aq.A16[2] = nullptr; aq.B[2] = wv16;
    aq.C[2] = vo16; aq.bias[2] = bo; aq.mode[2] = 4;

    dim3 gqkv(DD / TN, MM / TM, 3);   // (8, 128, 3)
    gemm_mma<<<gqkv, 256, GSMEM>>>(aq);

    kv_kernel<<<dim3(64, KV_SPLIT), 256>>>(ko16, vo16, gKVp, gKSp);
    kv_reduce<<<dim3(64, 4), 256>>>(gKVp, gKSp, gKV, gKS);
    attn_kernel<<<dim3(64, 8), 256>>>(qo16, gKV, gKS, a16);

    // output projection (+bias), fp16 A path unchanged
    GemmArgs ao;
    ao.A32[0] = nullptr; ao.A16[0] = a16; ao.B[0] = wo16;
    ao.C[0] = out; ao.bias[0] = bo; ao.mode[0] = 2;
    ao.A32[1] = nullptr; ao.A16[1] = a16; ao.B[1] = wo16;
    ao.C[1] = out; ao.bias[1] = bo; ao.mode[1] = 2;
    ao.A32[2] = nullptr; ao.A16[2] = a16; ao.B[2] = wo16;
    ao.C[2] = out; ao.bias[2] = bo; ao.mode[2] = 2;

    dim3 go(DD / TN, MM / TM, 1);     // (8, 128, 1)
    gemm_mma<<<go, 256, GSMEM>>>(ao);
}

// round 13
// speedup vs baseline: 1.0695x; 1.0695x over previous
#include <cuda_runtime.h>
#include <cuda_fp16.h>
#include <cstdint>
#include <cstddef>

// Problem constants
#define BB 4
#define SS 4096
#define DD 1024
#define HH 16
#define DK 64
#define MM (BB * SS)          // 16384

// ---------------- scratch (device globals; no runtime allocation) ----------
__device__ __half g_q16[(size_t)MM * DD];
__device__ __half g_k16[(size_t)MM * DD];
__device__ __half g_v16[(size_t)MM * DD];
__device__ __half g_a16[(size_t)MM * DD];
__device__ __half g_qo16[(size_t)MM * DD];   // projected Q (phi), fp16
__device__ __half g_ko16[(size_t)MM * DD];   // projected K (phi), fp16
__device__ __half g_vo16[(size_t)MM * DD];   // projected V, fp16

__device__ __half g_wq16[(size_t)DD * DD];
__device__ __half g_wk16[(size_t)DD * DD];
__device__ __half g_wv16[(size_t)DD * DD];
__device__ __half g_wo16[(size_t)DD * DD];

#define KV_SPLIT 16
__device__ float g_KVp[(size_t)KV_SPLIT * 64 * DK * DK];
__device__ float g_KSp[(size_t)KV_SPLIT * 64 * DK];
__device__ float g_KV[(size_t)64 * DK * DK];
__device__ float g_KS[(size_t)64 * DK];

// ============================ PTX helpers ==================================
__device__ __forceinline__ uint32_t s2u(const void* p) {
    uint32_t a;
    asm("{ .reg .u64 t; cvta.to.shared.u64 t, %1; cvt.u32.u64 %0, t; }"
        : "=r"(a) : "l"(p));
    return a;
}

__device__ __forceinline__ void cp16(uint32_t dst, const void* src) {
    asm volatile("cp.async.cg.shared.global [%0], [%1], 16;"
                 :: "r"(dst), "l"(src) : "memory");
}

#define LDSM4(r, addr)                                                         \
    asm volatile("ldmatrix.sync.aligned.m8n8.x4.shared.b16 "                   \
                 "{%0,%1,%2,%3}, [%4];"                                        \
                 : "=r"((r)[0]), "=r"((r)[1]), "=r"((r)[2]), "=r"((r)[3])      \
                 : "r"(addr))

#define MMA16816(d, a, b)                                                      \
    asm volatile("mma.sync.aligned.m16n8k16.row.col.f32.f16.f16.f32 "          \
                 "{%0,%1,%2,%3}, {%4,%5,%6,%7}, {%8,%9}, {%0,%1,%2,%3};"       \
                 : "+f"((d)[0]), "+f"((d)[1]), "+f"((d)[2]), "+f"((d)[3])      \
                 : "r"((a)[0]), "r"((a)[1]), "r"((a)[2]), "r"((a)[3]),         \
                   "r"((b)[0]), "r"((b)[1]))

// ============================ fused conversion =============================
// One launch converts all 7 fp32 tensors to fp16 (flat float4-unit index).
struct ConvArgs {
    const float* src[7];
    __half* dst[7];
    int start[8];          // prefix sums, float4 units
};

__global__ void __launch_bounds__(256)
conv_all(ConvArgs a)
{
    const int u = blockIdx.x * blockDim.x + threadIdx.x;
    if (u >= a.start[7]) return;
    int t = 0;
#pragma unroll
    for (int j = 1; j < 7; j++) t += (u >= a.start[j]) ? 1 : 0;
    const int i = u - a.start[t];
    float4 v = ((const float4*)a.src[t])[i];
    __half2* yp = (__half2*)a.dst[t];
    yp[2 * i]     = __floats2half2_rn(v.x, v.y);
    yp[2 * i + 1] = __floats2half2_rn(v.z, v.w);
}

// ============================ mma.sync GEMM ================================
// C[m,n] = sum_k A[m,k]*W[n,k]. A and W single-rounded fp16, fp32 accumulate.
// mode: 0 plain->f32, 1 phi->f32, 2 +bias->f32, 3 phi->f16, 4 plain->f16
#define TM 128
#define TN 128
#define BKE 64                      // k elems per stage
#define KCH (DD / BKE)              // 16 chunks
#define RS 144                      // smem row stride bytes (128 data + 16 pad)
#define SPLIT_B (128 * RS)          // 18432
#define STAGE_B (2 * SPLIT_B)       // 36864 (A, W)
#define NST 3
#define GSMEM (NST * STAGE_B)       // 110592 -> 2 CTAs/SM (221KB)

struct GemmArgs {
    const __half* A[3];
    const __half* B[3];
    const float* bias[3];
    void* C[3];
    int mode[3];
};

__global__ void __launch_bounds__(256, 2)
gemm_mma(GemmArgs p)
{
    extern __shared__ char smem[];
    const uint32_t sb = s2u(smem);
    const int tid = threadIdx.x;
    const int lane = tid & 31;
    const int warp = tid >> 5;
    const int wm = warp & 3;        // 32-row slab
    const int wn = warp >> 2;       // 64-col slab
    const int z = blockIdx.z;
    const int bm = blockIdx.y * TM;
    const int bn = blockIdx.x * TN;
    const int mode = p.mode[z];

    const __half* gsrc[2];
    gsrc[0] = p.A[z] + (size_t)bm * DD;
    gsrc[1] = p.B[z] + (size_t)bn * DD;

    auto produce = [&](int c) {
        const uint32_t st = sb + (uint32_t)(c % NST) * STAGE_B;
#pragma unroll
        for (int it = 0; it < 8; it++) {
            const int li  = it * 256 + tid;     // 0..2047
            const int s   = li >> 10;           // split 0..1
            const int idx = li & 1023;
            const int r   = idx >> 3;           // row 0..127
            const int seg = idx & 7;            // 16B segment
            cp16(st + (uint32_t)(s * SPLIT_B + r * RS + seg * 16),
                 gsrc[s] + (size_t)r * DD + c * BKE + seg * 8);
        }
        asm volatile("cp.async.commit_group;" ::: "memory");
    };

    float acc[2][8][4];
#pragma unroll
    for (int i = 0; i < 2; i++)
#pragma unroll
        for (int j = 0; j < 8; j++)
#pragma unroll
            for (int k = 0; k < 4; k++) acc[i][j][k] = 0.0f;

    produce(0);
    produce(1);

    for (int c = 0; c < KCH; c++) {
        if (c == KCH - 1)
            asm volatile("cp.async.wait_group 0;" ::: "memory");
        else
            asm volatile("cp.async.wait_group 1;" ::: "memory");
        __syncthreads();
        if (c + 2 < KCH) produce(c + 2);

        const uint32_t st = sb + (uint32_t)(c % NST) * STAGE_B;
#pragma unroll
        for (int step = 0; step < 4; step++) {
            uint32_t ah[2][4], bh[8][2];
#pragma unroll
            for (int mt = 0; mt < 2; mt++) {
                const int row = wm * 32 + mt * 16 + (lane & 15);
                const uint32_t off =
                    (uint32_t)(row * RS + step * 32 + ((lane >> 4) & 1) * 16);
                LDSM4(ah[mt], st + off);
            }
#pragma unroll
            for (int nt2 = 0; nt2 < 4; nt2++) {
                const int nrow = wn * 64 + nt2 * 16 + (lane & 7) + ((lane >> 4) & 1) * 8;
                const uint32_t off =
                    (uint32_t)(nrow * RS + step * 32 + ((lane >> 3) & 1) * 16);
                uint32_t r[4];
                LDSM4(r, st + SPLIT_B + off);
                bh[nt2 * 2][0] = r[0]; bh[nt2 * 2][1] = r[1];
                bh[nt2 * 2 + 1][0] = r[2]; bh[nt2 * 2 + 1][1] = r[3];
            }
#pragma unroll
            for (int mt = 0; mt < 2; mt++)
#pragma unroll
                for (int nt = 0; nt < 8; nt++)
                    MMA16816(acc[mt][nt], ah[mt], bh[nt]);
        }
    }

    // epilogue
    const int gr = lane >> 2;        // 0..7
    const int gc = (lane & 3) * 2;   // 0,2,4,6
#pragma unroll
    for (int mt = 0; mt < 2; mt++) {
#pragma unroll
        for (int nt = 0; nt < 8; nt++) {
            const int row0 = bm + wm * 32 + mt * 16 + gr;
            const int col  = bn + wn * 64 + nt * 8 + gc;
            float v[4] = {acc[mt][nt][0], acc[mt][nt][1],
                          acc[mt][nt][2], acc[mt][nt][3]};
            if (mode == 1 || mode == 3) {
#pragma unroll
                for (int j = 0; j < 4; j++)
                    v[j] = (v[j] > 0.0f) ? (v[j] + 1.0f) : expf(v[j]);
            } else if (mode == 2) {
                const float b0 = p.bias[z][col], b1 = p.bias[z][col + 1];
                v[0] += b0; v[1] += b1; v[2] += b0; v[3] += b1;
            }
            if (mode <= 2) {
                float* C = (float*)p.C[z];
                float2 p0; p0.x = v[0]; p0.y = v[1];
                float2 p1; p1.x = v[2]; p1.y = v[3];
                *(float2*)(C + (size_t)row0 * DD + col) = p0;
                *(float2*)(C + (size_t)(row0 + 8) * DD + col) = p1;
            } else {
                __half* C = (__half*)p.C[z];
                *(__half2*)(C + (size_t)row0 * DD + col) =
                    __floats2half2_rn(v[0], v[1]);
                *(__half2*)(C + (size_t)(row0 + 8) * DD + col) =
                    __floats2half2_rn(v[2], v[3]);
            }
        }
    }
}

// ---------------- KV accumulation: KV[bh] = sum_s k(s) outer v(s) ----------
__global__ void __launch_bounds__(256)
kv_kernel(const __half* __restrict__ Kp, const __half* __restrict__ Vp,
          float* __restrict__ KVp, float* __restrict__ KSp)
{
    const int bh = blockIdx.x;          // 0..63
    const int sp = blockIdx.y;          // 0..KV_SPLIT-1
    const int b = bh >> 4, h = bh & 15;
    const int tid = threadIdx.x;
    const int tx = tid & 15;
    const int ty = tid >> 4;

    __shared__ float ks[8][68];
    __shared__ float vs[8][68];

    float acc[4][4];
#pragma unroll
    for (int i = 0; i < 4; i++)
#pragma unroll
        for (int j = 0; j < 4; j++) acc[i][j] = 0.0f;
    float kacc = 0.0f;

    const int sPer = SS / KV_SPLIT;     // 256
    const int sBase = sp * sPer;

    const int lrow = (tid >> 3) & 7;    // 0..7
    const int lseg = tid & 7;           // 0..7 (8 halves each)

    for (int s0 = 0; s0 < sPer; s0 += 8) {
        if (tid < 128) {
            const __half* src = (tid < 64) ? Kp : Vp;
            const size_t gaddr =
                ((size_t)(b * SS + sBase + s0 + lrow)) * DD + h * DK + lseg * 8;
            uint4 raw = *(const uint4*)(src + gaddr);
            const __half2* hp = (const __half2*)&raw;
            float2 f0 = __half22float2(hp[0]);
            float2 f1 = __half22float2(hp[1]);
            float2 f2 = __half22float2(hp[2]);
            float2 f3 = __half22float2(hp[3]);
            float* dst = (tid < 64) ? &ks[lrow][lseg * 8] : &vs[lrow][lseg * 8];
            float4 o0; o0.x = f0.x; o0.y = f0.y; o0.z = f1.x; o0.w = f1.y;
            float4 o1; o1.x = f2.x; o1.y = f2.y; o1.z = f3.x; o1.w = f3.y;
            *(float4*)(dst)     = o0;
            *(float4*)(dst + 4) = o1;
        }
        __syncthreads();

        if (tid < 64) {
#pragma unroll
            for (int j = 0; j < 8; j++) kacc += ks[j][tid];
        }
#pragma unroll
        for (int j = 0; j < 8; j++) {
            float4 av = *(const float4*)&ks[j][ty * 4];
            float4 bv = *(const float4*)&vs[j][tx * 4];
            float a[4] = {av.x, av.y, av.z, av.w};
            float c[4] = {bv.x, bv.y, bv.z, bv.w};
#pragma unroll
            for (int i = 0; i < 4; i++)
#pragma unroll
                for (int jj = 0; jj < 4; jj++)
                    acc[i][jj] += a[i] * c[jj];
        }
        __syncthreads();
    }

    float* outp = KVp + ((size_t)(sp * 64 + bh)) * (DK * DK);
#pragma unroll
    for (int i = 0; i < 4; i++)
#pragma unroll
        for (int jj = 0; jj < 4; jj++)
            outp[(ty * 4 + i) * DK + tx * 4 + jj] = acc[i][jj];

    if (tid < 64)
        KSp[((size_t)(sp * 64 + bh)) * DK + tid] = kacc;
}

// ---------------- parallel reduce of KV partials ---------------------------
// grid (64, 4): each block sums 256 float4 of one head's KV + (y==0) KS.
__global__ void __launch_bounds__(256)
kv_reduce(const float* __restrict__ KVp, const float* __restrict__ KSp,
          float* __restrict__ KV, float* __restrict__ KS)
{
    const int bh = blockIdx.x;
    const int part = blockIdx.y;        // 0..3
    const int tid = threadIdx.x;
    const int e4 = part * 256 + tid;    // float4 index 0..1023

    const float4* src = (const float4*)KVp;
    float4 s; s.x = 0.f; s.y = 0.f; s.z = 0.f; s.w = 0.f;
#pragma unroll
    for (int r = 0; r < KV_SPLIT; r++) {
        float4 v = src[((size_t)(r * 64 + bh)) * (DK * DK / 4) + e4];
        s.x += v.x; s.y += v.y; s.z += v.z; s.w += v.w;
    }
    ((float4*)KV)[(size_t)bh * (DK * DK / 4) + e4] = s;

    if (part == 0 && tid < DK) {
        float t = 0.0f;
#pragma unroll
        for (int r = 0; r < KV_SPLIT; r++)
            t += KSp[((size_t)(r * 64 + bh)) * DK + tid];
        KS[(size_t)bh * DK + tid] = t;
    }
}

// ---------------- attention normalize: fp16 Q -> fp16 output ---------------
__global__ void __launch_bounds__(256)
attn_kernel(const __half* __restrict__ Q16, const float* __restrict__ KV,
            const float* __restrict__ KS, __half* __restrict__ A16)
{
    const int bh = blockIdx.x;          // 0..63
    const int sc = blockIdx.y;          // 0..7 (512 rows per block)
    const int b = bh >> 4, h = bh & 15;
    const int tid = threadIdx.x;
    const int w = tid >> 5, l = tid & 31;

    __shared__ float KVs[DK * DK];
    __shared__ float KSs[DK];
    __shared__ float qb[8][8][64];      // [warp][row][dk]

    for (int i = tid; i < (DK * DK) / 4; i += 256)
        ((float4*)KVs)[i] = ((const float4*)(KV + (size_t)bh * DK * DK))[i];
    if (tid < DK) KSs[tid] = KS[(size_t)bh * DK + tid];
    __syncthreads();

    const size_t qbase = ((size_t)(b * SS) + sc * 512 + w * 64) * DD + h * DK;

    for (int g = 0; g < 8; g++) {
        const __half* qrow = Q16 + qbase + (size_t)(g * 8) * DD;
#pragma unroll
        for (int t = 0; t < 2; t++) {
            const int idx = l + t * 32;           // 0..63
            const int r = idx >> 3, seg = idx & 7;
            uint4 raw = *(const uint4*)(qrow + (size_t)r * DD + seg * 8);
            const __half2* hp = (const __half2*)&raw;
            float2 f0 = __half22float2(hp[0]);
            float2 f1 = __half22float2(hp[1]);
            float2 f2 = __half22float2(hp[2]);
            float2 f3 = __half22float2(hp[3]);
            float* dst = &qb[w][r][seg * 8];
            float4 o0; o0.x = f0.x; o0.y = f0.y; o0.z = f1.x; o0.w = f1.y;
            float4 o1; o1.x = f2.x; o1.y = f2.y; o1.z = f3.x; o1.w = f3.y;
            *(float4*)(dst)     = o0;
            *(float4*)(dst + 4) = o1;
        }
        __syncwarp();

        float n0[8], n1[8], dn[8];
#pragma unroll
        for (int r = 0; r < 8; r++) { n0[r] = 0.f; n1[r] = 0.f; dn[r] = 0.f; }
#pragma unroll
        for (int dk = 0; dk < DK; dk++) {
            const float kv0 = KVs[dk * DK + l];
            const float kv1 = KVs[dk * DK + l + 32];
            const float ksv = KSs[dk];
#pragma unroll
            for (int r = 0; r < 8; r++) {
                const float q = qb[w][r][dk];
                n0[r] += q * kv0;
                n1[r] += q * kv1;
                dn[r] += q * ksv;
            }
        }
#pragma unroll
        for (int r = 0; r < 8; r++) {
            const size_t orow = qbase + (size_t)(g * 8 + r) * DD;
            const float inv = 1.0f / (dn[r] + 1e-6f);
            A16[orow + l]      = __float2half_rn(n0[r] * inv);
            A16[orow + l + 32] = __float2half_rn(n1[r] * inv);
        }
        __syncwarp();
    }
}

// ---------------- launch ---------------------------------------------------
extern "C" void kernel_launch(void* const* d_in, const int* in_sizes, int n_in,
                              void* d_out, int out_size)
{
    const float* query = (const float*)d_in[0];
    const float* key   = (const float*)d_in[1];
    const float* value = (const float*)d_in[2];
    const float* Wq    = (const float*)d_in[3];
    const float* Wk    = (const float*)d_in[4];
    const float* Wv    = (const float*)d_in[5];
    const float* Wo    = (const float*)d_in[6];
    const float* bo    = (const float*)d_in[7];
    float* out = (float*)d_out;

    float *gKVp, *gKSp, *gKV, *gKS;
    __half *q16, *k16, *v16, *a16, *qo16, *ko16, *vo16;
    __half *wq16, *wk16, *wv16, *wo16;
    cudaGetSymbolAddress((void**)&gKVp, g_KVp);
    cudaGetSymbolAddress((void**)&gKSp, g_KSp);
    cudaGetSymbolAddress((void**)&gKV, g_KV);
    cudaGetSymbolAddress((void**)&gKS, g_KS);
    cudaGetSymbolAddress((void**)&q16, g_q16);
    cudaGetSymbolAddress((void**)&k16, g_k16);
    cudaGetSymbolAddress((void**)&v16, g_v16);
    cudaGetSymbolAddress((void**)&a16, g_a16);
    cudaGetSymbolAddress((void**)&qo16, g_qo16);
    cudaGetSymbolAddress((void**)&ko16, g_ko16);
    cudaGetSymbolAddress((void**)&vo16, g_vo16);
    cudaGetSymbolAddress((void**)&wq16, g_wq16);
    cudaGetSymbolAddress((void**)&wk16, g_wk16);
    cudaGetSymbolAddress((void**)&wv16, g_wv16);
    cudaGetSymbolAddress((void**)&wo16, g_wo16);

    cudaFuncSetAttribute(gemm_mma, cudaFuncAttributeMaxDynamicSharedMemorySize,
                         GSMEM);

    // single fused conversion launch (3 activations + 4 weights)
    const int nAct4 = (MM * DD) / 4;   // 4194304
    const int nW4   = (DD * DD) / 4;   // 262144
    ConvArgs ca;
    ca.src[0] = query; ca.dst[0] = q16;
    ca.src[1] = key;   ca.dst[1] = k16;
    ca.src[2] = value; ca.dst[2] = v16;
    ca.src[3] = Wq;    ca.dst[3] = wq16;
    ca.src[4] = Wk;    ca.dst[4] = wk16;
    ca.src[5] = Wv;    ca.dst[5] = wv16;
    ca.src[6] = Wo;    ca.dst[6] = wo16;
    ca.start[0] = 0;
    ca.start[1] = nAct4;
    ca.start[2] = 2 * nAct4;
    ca.start[3] = 3 * nAct4;
    ca.start[4] = 3 * nAct4 + nW4;
    ca.start[5] = 3 * nAct4 + 2 * nW4;
    ca.start[6] = 3 * nAct4 + 3 * nW4;
    ca.start[7] = 3 * nAct4 + 4 * nW4;
    conv_all<<<(ca.start[7] + 255) / 256, 256>>>(ca);

    // fused Q/K/V projections; all three written directly as fp16
    GemmArgs aq;
    aq.A[0] = q16; aq.B[0] = wq16; aq.C[0] = qo16; aq.bias[0] = bo; aq.mode[0] = 3;
    aq.A[1] = k16; aq.B[1] = wk16; aq.C[1] = ko16; aq.bias[1] = bo; aq.mode[1] = 3;
    aq.A[2] = v16; aq.B[2] = wv16; aq.C[2] = vo16; aq.bias[2] = bo; aq.mode[2] = 4;

    dim3 gqkv(DD / TN, MM / TM, 3);   // (8, 128, 3)
    gemm_mma<<<gqkv, 256, GSMEM>>>(aq);

    kv_kernel<<<dim3(64, KV_SPLIT), 256>>>(ko16, vo16, gKVp, gKSp);
    kv_reduce<<<dim3(64, 4), 256>>>(gKVp, gKSp, gKV, gKS);
    attn_kernel<<<dim3(64, 8), 256>>>(qo16, gKV, gKS, a16);

    // output projection (+bias)
    GemmArgs ao;
    ao.A[0] = a16; ao.B[0] = wo16; ao.C[0] = out; ao.bias[0] = bo; ao.mode[0] = 2;
    ao.A[1] = a16; ao.B[1] = wo16; ao.C[1] = out; ao.bias[1] = bo; ao.mode[1] = 2;
    ao.A[2] = a16; ao.B[2] = wo16; ao.C[2] = out; ao.bias[2] = bo; ao.mode[2] = 2;

    dim3 go(DD / TN, MM / TM, 1);     // (8, 128, 1)
    gemm_mma<<<go, 256, GSMEM>>>(ao);
}

// round 14
// speedup vs baseline: 1.0966x; 1.0254x over previous
#include <cuda_runtime.h>
#include <cuda_fp16.h>
#include <cstdint>
#include <cstddef>

// Problem constants
#define BB 4
#define SS 4096
#define DD 1024
#define HH 16
#define DK 64
#define MM (BB * SS)          // 16384

// ---------------- scratch (device globals; no runtime allocation) ----------
__device__ __half g_q16[(size_t)MM * DD];
__device__ __half g_k16[(size_t)MM * DD];
__device__ __half g_v16[(size_t)MM * DD];
__device__ __half g_a16[(size_t)MM * DD];
__device__ __half g_qo16[(size_t)MM * DD];   // projected Q (phi), fp16
__device__ __half g_ko16[(size_t)MM * DD];   // projected K (phi), fp16
__device__ __half g_vo16[(size_t)MM * DD];   // projected V, fp16

__device__ __half g_wq16[(size_t)DD * DD];
__device__ __half g_wk16[(size_t)DD * DD];
__device__ __half g_wv16[(size_t)DD * DD];
__device__ __half g_wo16[(size_t)DD * DD];

#define KV_SPLIT 32
__device__ float g_KVp[(size_t)KV_SPLIT * 64 * DK * DK];
__device__ float g_KSp[(size_t)KV_SPLIT * 64 * DK];
__device__ float g_KV[(size_t)64 * DK * DK];
__device__ float g_KS[(size_t)64 * DK];

// ============================ PTX helpers ==================================
__device__ __forceinline__ uint32_t s2u(const void* p) {
    uint32_t a;
    asm("{ .reg .u64 t; cvta.to.shared.u64 t, %1; cvt.u32.u64 %0, t; }"
        : "=r"(a) : "l"(p));
    return a;
}

__device__ __forceinline__ void cp16(uint32_t dst, const void* src) {
    asm volatile("cp.async.cg.shared.global [%0], [%1], 16;"
                 :: "r"(dst), "l"(src) : "memory");
}

#define LDSM4(r, addr)                                                         \
    asm volatile("ldmatrix.sync.aligned.m8n8.x4.shared.b16 "                   \
                 "{%0,%1,%2,%3}, [%4];"                                        \
                 : "=r"((r)[0]), "=r"((r)[1]), "=r"((r)[2]), "=r"((r)[3])      \
                 : "r"(addr))

#define MMA16816(d, a, b)                                                      \
    asm volatile("mma.sync.aligned.m16n8k16.row.col.f32.f16.f16.f32 "          \
                 "{%0,%1,%2,%3}, {%4,%5,%6,%7}, {%8,%9}, {%0,%1,%2,%3};"       \
                 : "+f"((d)[0]), "+f"((d)[1]), "+f"((d)[2]), "+f"((d)[3])      \
                 : "r"((a)[0]), "r"((a)[1]), "r"((a)[2]), "r"((a)[3]),         \
                   "r"((b)[0]), "r"((b)[1]))

// ============================ fused conversion =============================
struct ConvArgs {
    const float* src[7];
    __half* dst[7];
    int start[8];          // prefix sums, float4 units
};

__global__ void __launch_bounds__(256)
conv_all(ConvArgs a)
{
    const int u = blockIdx.x * blockDim.x + threadIdx.x;
    if (u >= a.start[7]) return;
    int t = 0;
#pragma unroll
    for (int j = 1; j < 7; j++) t += (u >= a.start[j]) ? 1 : 0;
    const int i = u - a.start[t];
    float4 v = ((const float4*)a.src[t])[i];
    __half2* yp = (__half2*)a.dst[t];
    yp[2 * i]     = __floats2half2_rn(v.x, v.y);
    yp[2 * i + 1] = __floats2half2_rn(v.z, v.w);
}

// ============================ mma.sync GEMM ================================
// C[m,n] = sum_k A[m,k]*W[n,k]. A and W single-rounded fp16, fp32 accumulate.
// mode: 0 plain->f32, 1 phi->f32, 2 +bias->f32, 3 phi->f16, 4 plain->f16
#define TM 128
#define TN 128
#define BKE 64                      // k elems per stage
#define KCH (DD / BKE)              // 16 chunks
#define RS 144                      // smem row stride bytes (128 data + 16 pad)
#define SPLIT_B (128 * RS)          // 18432
#define STAGE_B (2 * SPLIT_B)       // 36864 (A, W)
#define NST 3
#define GSMEM (NST * STAGE_B)       // 110592 -> 2 CTAs/SM (221KB)

struct GemmArgs {
    const __half* A[3];
    const __half* B[3];
    const float* bias[3];
    void* C[3];
    int mode[3];
};

__global__ void __launch_bounds__(256, 2)
gemm_mma(GemmArgs p)
{
    extern __shared__ char smem[];
    const uint32_t sb = s2u(smem);
    const int tid = threadIdx.x;
    const int lane = tid & 31;
    const int warp = tid >> 5;
    const int wm = warp & 3;        // 32-row slab
    const int wn = warp >> 2;       // 64-col slab
    const int z = blockIdx.z;
    const int bm = blockIdx.y * TM;
    const int bn = blockIdx.x * TN;
    const int mode = p.mode[z];

    const __half* gsrc[2];
    gsrc[0] = p.A[z] + (size_t)bm * DD;
    gsrc[1] = p.B[z] + (size_t)bn * DD;

    auto produce = [&](int c) {
        const uint32_t st = sb + (uint32_t)(c % NST) * STAGE_B;
#pragma unroll
        for (int it = 0; it < 8; it++) {
            const int li  = it * 256 + tid;     // 0..2047
            const int s   = li >> 10;           // split 0..1
            const int idx = li & 1023;
            const int r   = idx >> 3;           // row 0..127
            const int seg = idx & 7;            // 16B segment
            cp16(st + (uint32_t)(s * SPLIT_B + r * RS + seg * 16),
                 gsrc[s] + (size_t)r * DD + c * BKE + seg * 8);
        }
        asm volatile("cp.async.commit_group;" ::: "memory");
    };

    float acc[2][8][4];
#pragma unroll
    for (int i = 0; i < 2; i++)
#pragma unroll
        for (int j = 0; j < 8; j++)
#pragma unroll
            for (int k = 0; k < 4; k++) acc[i][j][k] = 0.0f;

    produce(0);
    produce(1);

    for (int c = 0; c < KCH; c++) {
        if (c == KCH - 1)
            asm volatile("cp.async.wait_group 0;" ::: "memory");
        else
            asm volatile("cp.async.wait_group 1;" ::: "memory");
        __syncthreads();
        if (c + 2 < KCH) produce(c + 2);

        const uint32_t st = sb + (uint32_t)(c % NST) * STAGE_B;
#pragma unroll
        for (int step = 0; step < 4; step++) {
            uint32_t ah[2][4], bh[8][2];
#pragma unroll
            for (int mt = 0; mt < 2; mt++) {
                const int row = wm * 32 + mt * 16 + (lane & 15);
                const uint32_t off =
                    (uint32_t)(row * RS + step * 32 + ((lane >> 4) & 1) * 16);
                LDSM4(ah[mt], st + off);
            }
#pragma unroll
            for (int nt2 = 0; nt2 < 4; nt2++) {
                const int nrow = wn * 64 + nt2 * 16 + (lane & 7) + ((lane >> 4) & 1) * 8;
                const uint32_t off =
                    (uint32_t)(nrow * RS + step * 32 + ((lane >> 3) & 1) * 16);
                uint32_t r[4];
                LDSM4(r, st + SPLIT_B + off);
                bh[nt2 * 2][0] = r[0]; bh[nt2 * 2][1] = r[1];
                bh[nt2 * 2 + 1][0] = r[2]; bh[nt2 * 2 + 1][1] = r[3];
            }
#pragma unroll
            for (int mt = 0; mt < 2; mt++)
#pragma unroll
                for (int nt = 0; nt < 8; nt++)
                    MMA16816(acc[mt][nt], ah[mt], bh[nt]);
        }
    }

    // epilogue
    const int gr = lane >> 2;        // 0..7
    const int gc = (lane & 3) * 2;   // 0,2,4,6
#pragma unroll
    for (int mt = 0; mt < 2; mt++) {
#pragma unroll
        for (int nt = 0; nt < 8; nt++) {
            const int row0 = bm + wm * 32 + mt * 16 + gr;
            const int col  = bn + wn * 64 + nt * 8 + gc;
            float v[4] = {acc[mt][nt][0], acc[mt][nt][1],
                          acc[mt][nt][2], acc[mt][nt][3]};
            if (mode == 1 || mode == 3) {
#pragma unroll
                for (int j = 0; j < 4; j++)
                    v[j] = (v[j] > 0.0f) ? (v[j] + 1.0f) : expf(v[j]);
            } else if (mode == 2) {
                const float b0 = p.bias[z][col], b1 = p.bias[z][col + 1];
                v[0] += b0; v[1] += b1; v[2] += b0; v[3] += b1;
            }
            if (mode <= 2) {
                float* C = (float*)p.C[z];
                float2 p0; p0.x = v[0]; p0.y = v[1];
                float2 p1; p1.x = v[2]; p1.y = v[3];
                *(float2*)(C + (size_t)row0 * DD + col) = p0;
                *(float2*)(C + (size_t)(row0 + 8) * DD + col) = p1;
            } else {
                __half* C = (__half*)p.C[z];
                *(__half2*)(C + (size_t)row0 * DD + col) =
                    __floats2half2_rn(v[0], v[1]);
                *(__half2*)(C + (size_t)(row0 + 8) * DD + col) =
                    __floats2half2_rn(v[2], v[3]);
            }
        }
    }
}

// ---------------- KV accumulation: KV[bh] = sum_s k(s) outer v(s) ----------
__global__ void __launch_bounds__(256)
kv_kernel(const __half* __restrict__ Kp, const __half* __restrict__ Vp,
          float* __restrict__ KVp, float* __restrict__ KSp)
{
    const int bh = blockIdx.x;          // 0..63
    const int sp = blockIdx.y;          // 0..KV_SPLIT-1
    const int b = bh >> 4, h = bh & 15;
    const int tid = threadIdx.x;
    const int tx = tid & 15;
    const int ty = tid >> 4;

    __shared__ float ks[8][68];
    __shared__ float vs[8][68];

    float acc[4][4];
#pragma unroll
    for (int i = 0; i < 4; i++)
#pragma unroll
        for (int j = 0; j < 4; j++) acc[i][j] = 0.0f;
    float kacc = 0.0f;

    const int sPer = SS / KV_SPLIT;     // 128
    const int sBase = sp * sPer;

    const int lrow = (tid >> 3) & 7;    // 0..7
    const int lseg = tid & 7;           // 0..7 (8 halves each)

    for (int s0 = 0; s0 < sPer; s0 += 8) {
        if (tid < 128) {
            const __half* src = (tid < 64) ? Kp : Vp;
            const size_t gaddr =
                ((size_t)(b * SS + sBase + s0 + lrow)) * DD + h * DK + lseg * 8;
            uint4 raw = *(const uint4*)(src + gaddr);
            const __half2* hp = (const __half2*)&raw;
            float2 f0 = __half22float2(hp[0]);
            float2 f1 = __half22float2(hp[1]);
            float2 f2 = __half22float2(hp[2]);
            float2 f3 = __half22float2(hp[3]);
            float* dst = (tid < 64) ? &ks[lrow][lseg * 8] : &vs[lrow][lseg * 8];
            float4 o0; o0.x = f0.x; o0.y = f0.y; o0.z = f1.x; o0.w = f1.y;
            float4 o1; o1.x = f2.x; o1.y = f2.y; o1.z = f3.x; o1.w = f3.y;
            *(float4*)(dst)     = o0;
            *(float4*)(dst + 4) = o1;
        }
        __syncthreads();

        if (tid < 64) {
#pragma unroll
            for (int j = 0; j < 8; j++) kacc += ks[j][tid];
        }
#pragma unroll
        for (int j = 0; j < 8; j++) {
            float4 av = *(const float4*)&ks[j][ty * 4];
            float4 bv = *(const float4*)&vs[j][tx * 4];
            float a[4] = {av.x, av.y, av.z, av.w};
            float c[4] = {bv.x, bv.y, bv.z, bv.w};
#pragma unroll
            for (int i = 0; i < 4; i++)
#pragma unroll
                for (int jj = 0; jj < 4; jj++)
                    acc[i][jj] += a[i] * c[jj];
        }
        __syncthreads();
    }

    float* outp = KVp + ((size_t)(sp * 64 + bh)) * (DK * DK);
#pragma unroll
    for (int i = 0; i < 4; i++)
#pragma unroll
        for (int jj = 0; jj < 4; jj++)
            outp[(ty * 4 + i) * DK + tx * 4 + jj] = acc[i][jj];

    if (tid < 64)
        KSp[((size_t)(sp * 64 + bh)) * DK + tid] = kacc;
}

// ---------------- parallel reduce of KV partials ---------------------------
__global__ void __launch_bounds__(256)
kv_reduce(const float* __restrict__ KVp, const float* __restrict__ KSp,
          float* __restrict__ KV, float* __restrict__ KS)
{
    const int bh = blockIdx.x;
    const int part = blockIdx.y;        // 0..3
    const int tid = threadIdx.x;
    const int e4 = part * 256 + tid;    // float4 index 0..1023

    const float4* src = (const float4*)KVp;
    float4 s; s.x = 0.f; s.y = 0.f; s.z = 0.f; s.w = 0.f;
#pragma unroll
    for (int r = 0; r < KV_SPLIT; r++) {
        float4 v = src[((size_t)(r * 64 + bh)) * (DK * DK / 4) + e4];
        s.x += v.x; s.y += v.y; s.z += v.z; s.w += v.w;
    }
    ((float4*)KV)[(size_t)bh * (DK * DK / 4) + e4] = s;

    if (part == 0 && tid < DK) {
        float t = 0.0f;
#pragma unroll
        for (int r = 0; r < KV_SPLIT; r++)
            t += KSp[((size_t)(r * 64 + bh)) * DK + tid];
        KS[(size_t)bh * DK + tid] = t;
    }
}

// ---------------- attention normalize: fp16 Q -> fp16 output ---------------
__global__ void __launch_bounds__(256)
attn_kernel(const __half* __restrict__ Q16, const float* __restrict__ KV,
            const float* __restrict__ KS, __half* __restrict__ A16)
{
    const int bh = blockIdx.x;          // 0..63
    const int sc = blockIdx.y;          // 0..7 (512 rows per block)
    const int b = bh >> 4, h = bh & 15;
    const int tid = threadIdx.x;
    const int w = tid >> 5, l = tid & 31;

    __shared__ float KVs[DK * DK];
    __shared__ float KSs[DK];
    __shared__ float qb[8][8][64];      // [warp][row][dk]

    for (int i = tid; i < (DK * DK) / 4; i += 256)
        ((float4*)KVs)[i] = ((const float4*)(KV + (size_t)bh * DK * DK))[i];
    if (tid < DK) KSs[tid] = KS[(size_t)bh * DK + tid];
    __syncthreads();

    const size_t qbase = ((size_t)(b * SS) + sc * 512 + w * 64) * DD + h * DK;

    for (int g = 0; g < 8; g++) {
        const __half* qrow = Q16 + qbase + (size_t)(g * 8) * DD;
#pragma unroll
        for (int t = 0; t < 2; t++) {
            const int idx = l + t * 32;           // 0..63
            const int r = idx >> 3, seg = idx & 7;
            uint4 raw = *(const uint4*)(qrow + (size_t)r * DD + seg * 8);
            const __half2* hp = (const __half2*)&raw;
            float2 f0 = __half22float2(hp[0]);
            float2 f1 = __half22float2(hp[1]);
            float2 f2 = __half22float2(hp[2]);
            float2 f3 = __half22float2(hp[3]);
            float* dst = &qb[w][r][seg * 8];
            float4 o0; o0.x = f0.x; o0.y = f0.y; o0.z = f1.x; o0.w = f1.y;
            float4 o1; o1.x = f2.x; o1.y = f2.y; o1.z = f3.x; o1.w = f3.y;
            *(float4*)(dst)     = o0;
            *(float4*)(dst + 4) = o1;
        }
        __syncwarp();

        float n0[8], n1[8], dn[8];
#pragma unroll
        for (int r = 0; r < 8; r++) { n0[r] = 0.f; n1[r] = 0.f; dn[r] = 0.f; }
#pragma unroll
        for (int dk = 0; dk < DK; dk++) {
            const float kv0 = KVs[dk * DK + l];
            const float kv1 = KVs[dk * DK + l + 32];
            const float ksv = KSs[dk];
#pragma unroll
            for (int r = 0; r < 8; r++) {
                const float q = qb[w][r][dk];
                n0[r] += q * kv0;
                n1[r] += q * kv1;
                dn[r] += q * ksv;
            }
        }
#pragma unroll
        for (int r = 0; r < 8; r++) {
            const size_t orow = qbase + (size_t)(g * 8 + r) * DD;
            const float inv = 1.0f / (dn[r] + 1e-6f);
            A16[orow + l]      = __float2half_rn(n0[r] * inv);
            A16[orow + l + 32] = __float2half_rn(n1[r] * inv);
        }
        __syncwarp();
    }
}

// ---------------- launch ---------------------------------------------------
extern "C" void kernel_launch(void* const* d_in, const int* in_sizes, int n_in,
                              void* d_out, int out_size)
{
    const float* query = (const float*)d_in[0];
    const float* key   = (const float*)d_in[1];
    const float* value = (const float*)d_in[2];
    const float* Wq    = (const float*)d_in[3];
    const float* Wk    = (const float*)d_in[4];
    const float* Wv    = (const float*)d_in[5];
    const float* Wo    = (const float*)d_in[6];
    const float* bo    = (const float*)d_in[7];
    float* out = (float*)d_out;

    float *gKVp, *gKSp, *gKV, *gKS;
    __half *q16, *k16, *v16, *a16, *qo16, *ko16, *vo16;
    __half *wq16, *wk16, *wv16, *wo16;
    cudaGetSymbolAddress((void**)&gKVp, g_KVp);
    cudaGetSymbolAddress((void**)&gKSp, g_KSp);
    cudaGetSymbolAddress((void**)&gKV, g_KV);
    cudaGetSymbolAddress((void**)&gKS, g_KS);
    cudaGetSymbolAddress((void**)&q16, g_q16);
    cudaGetSymbolAddress((void**)&k16, g_k16);
    cudaGetSymbolAddress((void**)&v16, g_v16);
    cudaGetSymbolAddress((void**)&a16, g_a16);
    cudaGetSymbolAddress((void**)&qo16, g_qo16);
    cudaGetSymbolAddress((void**)&ko16, g_ko16);
    cudaGetSymbolAddress((void**)&vo16, g_vo16);
    cudaGetSymbolAddress((void**)&wq16, g_wq16);
    cudaGetSymbolAddress((void**)&wk16, g_wk16);
    cudaGetSymbolAddress((void**)&wv16, g_wv16);
    cudaGetSymbolAddress((void**)&wo16, g_wo16);

    cudaFuncSetAttribute(gemm_mma, cudaFuncAttributeMaxDynamicSharedMemorySize,
                         GSMEM);

    // one-time side stream + events for fork/join (work per call identical)
    static cudaStream_t s1 = nullptr;
    static cudaEvent_t evA = nullptr, evB = nullptr;
    if (s1 == nullptr) {
        cudaStreamCreateWithFlags(&s1, cudaStreamNonBlocking);
        cudaEventCreateWithFlags(&evA, cudaEventDisableTiming);
        cudaEventCreateWithFlags(&evB, cudaEventDisableTiming);
    }

    // single fused conversion launch (3 activations + 4 weights)
    const int nAct4 = (MM * DD) / 4;   // 4194304
    const int nW4   = (DD * DD) / 4;   // 262144
    ConvArgs ca;
    ca.src[0] = query; ca.dst[0] = q16;
    ca.src[1] = key;   ca.dst[1] = k16;
    ca.src[2] = value; ca.dst[2] = v16;
    ca.src[3] = Wq;    ca.dst[3] = wq16;
    ca.src[4] = Wk;    ca.dst[4] = wk16;
    ca.src[5] = Wv;    ca.dst[5] = wv16;
    ca.src[6] = Wo;    ca.dst[6] = wo16;
    ca.start[0] = 0;
    ca.start[1] = nAct4;
    ca.start[2] = 2 * nAct4;
    ca.start[3] = 3 * nAct4;
    ca.start[4] = 3 * nAct4 + nW4;
    ca.start[5] = 3 * nAct4 + 2 * nW4;
    ca.start[6] = 3 * nAct4 + 3 * nW4;
    ca.start[7] = 3 * nAct4 + 4 * nW4;
    conv_all<<<(ca.start[7] + 255) / 256, 256>>>(ca);

    // fork: Q projection on side stream, K/V projections + kv chain on main
    cudaEventRecord(evA, 0);
    cudaStreamWaitEvent(s1, evA, 0);

    GemmArgs aQ;
    aQ.A[0] = q16; aQ.B[0] = wq16; aQ.C[0] = qo16; aQ.bias[0] = bo; aQ.mode[0] = 3;
    aQ.A[1] = q16; aQ.B[1] = wq16; aQ.C[1] = qo16; aQ.bias[1] = bo; aQ.mode[1] = 3;
    aQ.A[2] = q16; aQ.B[2] = wq16; aQ.C[2] = qo16; aQ.bias[2] = bo; aQ.mode[2] = 3;
    gemm_mma<<<dim3(DD / TN, MM / TM, 1), 256, GSMEM, s1>>>(aQ);
    cudaEventRecord(evB, s1);

    GemmArgs aKV;
    aKV.A[0] = k16; aKV.B[0] = wk16; aKV.C[0] = ko16; aKV.bias[0] = bo; aKV.mode[0] = 3;
    aKV.A[1] = v16; aKV.B[1] = wv16; aKV.C[1] = vo16; aKV.bias[1] = bo; aKV.mode[1] = 4;
    aKV.A[2] = k16; aKV.B[2] = wk16; aKV.C[2] = ko16; aKV.bias[2] = bo; aKV.mode[2] = 3;
    gemm_mma<<<dim3(DD / TN, MM / TM, 2), 256, GSMEM>>>(aKV);

    kv_kernel<<<dim3(64, KV_SPLIT), 256>>>(ko16, vo16, gKVp, gKSp);
    kv_reduce<<<dim3(64, 4), 256>>>(gKVp, gKSp, gKV, gKS);

    // join: attn needs Q projection + reduced KV
    cudaStreamWaitEvent(0, evB, 0);
    attn_kernel<<<dim3(64, 8), 256>>>(qo16, gKV, gKS, a16);

    // output projection (+bias)
    GemmArgs ao;
    ao.A[0] = a16; ao.B[0] = wo16; ao.C[0] = out; ao.bias[0] = bo; ao.mode[0] = 2;
    ao.A[1] = a16; ao.B[1] = wo16; ao.C[1] = out; ao.bias[1] = bo; ao.mode[1] = 2;
    ao.A[2] = a16; ao.B[2] = wo16; ao.C[2] = out; ao.bias[2] = bo; ao.mode[2] = 2;
    gemm_mma<<<dim3(DD / TN, MM / TM, 1), 256, GSMEM>>>(ao);
}

// round 15
// speedup vs baseline: 1.2313x; 1.1228x over previous
#include <cuda_runtime.h>
#include <cuda_fp16.h>
#include <cstdint>
#include <cstddef>

// Problem constants
#define BB 4
#define SS 4096
#define DD 1024
#define HH 16
#define DK 64
#define MM (BB * SS)          // 16384

// ---------------- scratch (device globals; no runtime allocation) ----------
__device__ __half g_q16[(size_t)MM * DD];
__device__ __half g_k16[(size_t)MM * DD];
__device__ __half g_v16[(size_t)MM * DD];
__device__ __half g_a16[(size_t)MM * DD];
__device__ __half g_qo16[(size_t)MM * DD];   // projected Q (phi), fp16
__device__ __half g_ko16[(size_t)MM * DD];   // projected K (phi), fp16
__device__ __half g_vo16[(size_t)MM * DD];   // projected V, fp16

__device__ __half g_wq16[(size_t)DD * DD];
__device__ __half g_wk16[(size_t)DD * DD];
__device__ __half g_wv16[(size_t)DD * DD];
__device__ __half g_wo16[(size_t)DD * DD];

#define KSPL 8
__device__ float g_KVp[(size_t)KSPL * 64 * DK * DK];
__device__ float g_KSp[(size_t)KSPL * 64 * DK];
__device__ float g_KV[(size_t)64 * DK * DK];
__device__ float g_KS[(size_t)64 * DK];

// ============================ PTX helpers ==================================
__device__ __forceinline__ uint32_t s2u(const void* p) {
    uint32_t a;
    asm("{ .reg .u64 t; cvta.to.shared.u64 t, %1; cvt.u32.u64 %0, t; }"
        : "=r"(a) : "l"(p));
    return a;
}

__device__ __forceinline__ void cp16(uint32_t dst, const void* src) {
    asm volatile("cp.async.cg.shared.global [%0], [%1], 16;"
                 :: "r"(dst), "l"(src) : "memory");
}

#define LDSM4(r, addr)                                                         \
    asm volatile("ldmatrix.sync.aligned.m8n8.x4.shared.b16 "                   \
                 "{%0,%1,%2,%3}, [%4];"                                        \
                 : "=r"((r)[0]), "=r"((r)[1]), "=r"((r)[2]), "=r"((r)[3])      \
                 : "r"(addr))

#define LDSM4T(r, addr)                                                        \
    asm volatile("ldmatrix.sync.aligned.m8n8.x4.trans.shared.b16 "             \
                 "{%0,%1,%2,%3}, [%4];"                                        \
                 : "=r"((r)[0]), "=r"((r)[1]), "=r"((r)[2]), "=r"((r)[3])      \
                 : "r"(addr))

#define MMA16816(d, a, b)                                                      \
    asm volatile("mma.sync.aligned.m16n8k16.row.col.f32.f16.f16.f32 "          \
                 "{%0,%1,%2,%3}, {%4,%5,%6,%7}, {%8,%9}, {%0,%1,%2,%3};"       \
                 : "+f"((d)[0]), "+f"((d)[1]), "+f"((d)[2]), "+f"((d)[3])      \
                 : "r"((a)[0]), "r"((a)[1]), "r"((a)[2]), "r"((a)[3]),         \
                   "r"((b)[0]), "r"((b)[1]))

// ============================ fused conversion =============================
struct ConvArgs {
    const float* src[7];
    __half* dst[7];
    int start[8];          // prefix sums, float4 units
};

__global__ void __launch_bounds__(256)
conv_all(ConvArgs a)
{
    const int u = blockIdx.x * blockDim.x + threadIdx.x;
    if (u >= a.start[7]) return;
    int t = 0;
#pragma unroll
    for (int j = 1; j < 7; j++) t += (u >= a.start[j]) ? 1 : 0;
    const int i = u - a.start[t];
    float4 v = ((const float4*)a.src[t])[i];
    __half2* yp = (__half2*)a.dst[t];
    yp[2 * i]     = __floats2half2_rn(v.x, v.y);
    yp[2 * i + 1] = __floats2half2_rn(v.z, v.w);
}

// ============================ mma.sync GEMM ================================
// mode: 0 plain->f32, 1 phi->f32, 2 +bias->f32, 3 phi->f16, 4 plain->f16
#define TM 128
#define TN 128
#define BKE 64                      // k elems per stage
#define KCH (DD / BKE)              // 16 chunks
#define RS 144                      // smem row stride bytes (128 data + 16 pad)
#define SPLIT_B (128 * RS)          // 18432
#define STAGE_B (2 * SPLIT_B)       // 36864 (A, W)
#define NST 3
#define GSMEM (NST * STAGE_B)       // 110592 -> 2 CTAs/SM (221KB)

struct GemmArgs {
    const __half* A[3];
    const __half* B[3];
    const float* bias[3];
    void* C[3];
    int mode[3];
};

__global__ void __launch_bounds__(256, 2)
gemm_mma(GemmArgs p)
{
    extern __shared__ char smem[];
    const uint32_t sb = s2u(smem);
    const int tid = threadIdx.x;
    const int lane = tid & 31;
    const int warp = tid >> 5;
    const int wm = warp & 3;        // 32-row slab
    const int wn = warp >> 2;       // 64-col slab
    const int z = blockIdx.z;
    const int bm = blockIdx.y * TM;
    const int bn = blockIdx.x * TN;
    const int mode = p.mode[z];

    const __half* gsrc[2];
    gsrc[0] = p.A[z] + (size_t)bm * DD;
    gsrc[1] = p.B[z] + (size_t)bn * DD;

    auto produce = [&](int c) {
        const uint32_t st = sb + (uint32_t)(c % NST) * STAGE_B;
#pragma unroll
        for (int it = 0; it < 8; it++) {
            const int li  = it * 256 + tid;     // 0..2047
            const int s   = li >> 10;           // split 0..1
            const int idx = li & 1023;
            const int r   = idx >> 3;           // row 0..127
            const int seg = idx & 7;            // 16B segment
            cp16(st + (uint32_t)(s * SPLIT_B + r * RS + seg * 16),
                 gsrc[s] + (size_t)r * DD + c * BKE + seg * 8);
        }
        asm volatile("cp.async.commit_group;" ::: "memory");
    };

    float acc[2][8][4];
#pragma unroll
    for (int i = 0; i < 2; i++)
#pragma unroll
        for (int j = 0; j < 8; j++)
#pragma unroll
            for (int k = 0; k < 4; k++) acc[i][j][k] = 0.0f;

    produce(0);
    produce(1);

    for (int c = 0; c < KCH; c++) {
        if (c == KCH - 1)
            asm volatile("cp.async.wait_group 0;" ::: "memory");
        else
            asm volatile("cp.async.wait_group 1;" ::: "memory");
        __syncthreads();
        if (c + 2 < KCH) produce(c + 2);

        const uint32_t st = sb + (uint32_t)(c % NST) * STAGE_B;
#pragma unroll
        for (int step = 0; step < 4; step++) {
            uint32_t ah[2][4], bh[8][2];
#pragma unroll
            for (int mt = 0; mt < 2; mt++) {
                const int row = wm * 32 + mt * 16 + (lane & 15);
                const uint32_t off =
                    (uint32_t)(row * RS + step * 32 + ((lane >> 4) & 1) * 16);
                LDSM4(ah[mt], st + off);
            }
#pragma unroll
            for (int nt2 = 0; nt2 < 4; nt2++) {
                const int nrow = wn * 64 + nt2 * 16 + (lane & 7) + ((lane >> 4) & 1) * 8;
                const uint32_t off =
                    (uint32_t)(nrow * RS + step * 32 + ((lane >> 3) & 1) * 16);
                uint32_t r[4];
                LDSM4(r, st + SPLIT_B + off);
                bh[nt2 * 2][0] = r[0]; bh[nt2 * 2][1] = r[1];
                bh[nt2 * 2 + 1][0] = r[2]; bh[nt2 * 2 + 1][1] = r[3];
            }
#pragma unroll
            for (int mt = 0; mt < 2; mt++)
#pragma unroll
                for (int nt = 0; nt < 8; nt++)
                    MMA16816(acc[mt][nt], ah[mt], bh[nt]);
        }
    }

    // epilogue
    const int gr = lane >> 2;        // 0..7
    const int gc = (lane & 3) * 2;   // 0,2,4,6
#pragma unroll
    for (int mt = 0; mt < 2; mt++) {
#pragma unroll
        for (int nt = 0; nt < 8; nt++) {
            const int row0 = bm + wm * 32 + mt * 16 + gr;
            const int col  = bn + wn * 64 + nt * 8 + gc;
            float v[4] = {acc[mt][nt][0], acc[mt][nt][1],
                          acc[mt][nt][2], acc[mt][nt][3]};
            if (mode == 1 || mode == 3) {
#pragma unroll
                for (int j = 0; j < 4; j++)
                    v[j] = (v[j] > 0.0f) ? (v[j] + 1.0f) : expf(v[j]);
            } else if (mode == 2) {
                const float b0 = p.bias[z][col], b1 = p.bias[z][col + 1];
                v[0] += b0; v[1] += b1; v[2] += b0; v[3] += b1;
            }
            if (mode <= 2) {
                float* C = (float*)p.C[z];
                float2 p0; p0.x = v[0]; p0.y = v[1];
                float2 p1; p1.x = v[2]; p1.y = v[3];
                *(float2*)(C + (size_t)row0 * DD + col) = p0;
                *(float2*)(C + (size_t)(row0 + 8) * DD + col) = p1;
            } else {
                __half* C = (__half*)p.C[z];
                *(__half2*)(C + (size_t)row0 * DD + col) =
                    __floats2half2_rn(v[0], v[1]);
                *(__half2*)(C + (size_t)(row0 + 8) * DD + col) =
                    __floats2half2_rn(v[2], v[3]);
            }
        }
    }
}

// ---------------- tensor-core KV accumulation ------------------------------
// KV[bh][d][e] = sum_s K[s,d]*V[s,e] via m16n8k16 MMA; Ksum[d] alongside.
// grid (64, KSPL), 256 threads (8 warps, 2x4 over the 64x64 tile).
#define KRS 144
#define KTILE_B (64 * KRS)          // 9216
#define KVSTG (2 * KTILE_B)         // 18432
#define KVNST 3
#define KVSMEM (KVNST * KVSTG)      // 55296
#define KVNC ((SS / KSPL) / 64)     // 8 chunks of 64 s

__global__ void __launch_bounds__(256)
kv_tc(const __half* __restrict__ Kp, const __half* __restrict__ Vp,
      float* __restrict__ KVp, float* __restrict__ KSp)
{
    extern __shared__ char smem[];
    const uint32_t sb = s2u(smem);
    const int bh = blockIdx.x, sp = blockIdx.y;
    const int b = bh >> 4, h = bh & 15;
    const int tid = threadIdx.x, lane = tid & 31, warp = tid >> 5;
    const int wm = warp & 1;        // m-half (32 rows of d)
    const int wn = warp >> 1;       // n-quarter (16 cols of e)
    const int sBase = sp * (SS / KSPL);

    const __half* gK = Kp + ((size_t)(b * SS + sBase)) * DD + h * DK;
    const __half* gV = Vp + ((size_t)(b * SS + sBase)) * DD + h * DK;

    auto produce = [&](int c) {
        const uint32_t st = sb + (uint32_t)(c % KVNST) * KVSTG;
#pragma unroll
        for (int it = 0; it < 4; it++) {
            const int li = it * 256 + tid;      // 0..1023
            const int ts = li >> 9;             // 0:K 1:V
            const int idx = li & 511;
            const int r = idx >> 3, seg = idx & 7;
            const __half* g = (ts ? gV : gK) + ((size_t)(c * 64 + r)) * DD + seg * 8;
            cp16(st + (uint32_t)(ts * KTILE_B + r * KRS + seg * 16), g);
        }
        asm volatile("cp.async.commit_group;" ::: "memory");
    };

    float acc[2][2][4];
#pragma unroll
    for (int i = 0; i < 2; i++)
#pragma unroll
        for (int j = 0; j < 2; j++)
#pragma unroll
            for (int k = 0; k < 4; k++) acc[i][j][k] = 0.0f;
    float kacc = 0.0f;

    produce(0);
    produce(1);

    for (int c = 0; c < KVNC; c++) {
        if (c == KVNC - 1)
            asm volatile("cp.async.wait_group 0;" ::: "memory");
        else
            asm volatile("cp.async.wait_group 1;" ::: "memory");
        __syncthreads();
        if (c + 2 < KVNC) produce(c + 2);

        const uint32_t stb = (uint32_t)(c % KVNST) * KVSTG;
        const uint32_t st = sb + stb;

        // Ksum partial (threads 0..63 each own one d-column)
        if (tid < 64) {
#pragma unroll
            for (int r = 0; r < 64; r++)
                kacc += __half2float(
                    *(const __half*)(smem + stb + r * KRS + tid * 2));
        }

#pragma unroll
        for (int ks = 0; ks < 4; ks++) {
            const int s0 = ks * 16;
            uint32_t a[2][4], bb[2][2];
            // A = K^T fragments: addressed [s][d] tile, trans ldmatrix.
            // lane bits: bit3 = m-half, bit4 = k-half
#pragma unroll
            for (int mt = 0; mt < 2; mt++) {
                const int m0 = wm * 32 + mt * 16;
                const int row = s0 + (lane & 7) + ((lane >> 4) & 1) * 8;
                const int col = m0 + ((lane >> 3) & 1) * 8;
                LDSM4T(a[mt], st + (uint32_t)(row * KRS + col * 2));
            }
            // B = V fragments (col-major): lane bits: bit3 = k-half, bit4 = n-half
            {
                const int n0 = wn * 16;
                const int row = s0 + (lane & 7) + ((lane >> 3) & 1) * 8;
                const int col = n0 + ((lane >> 4) & 1) * 8;
                uint32_t r4[4];
                LDSM4T(r4, st + (uint32_t)(KTILE_B + row * KRS + col * 2));
                bb[0][0] = r4[0]; bb[0][1] = r4[1];
                bb[1][0] = r4[2]; bb[1][1] = r4[3];
            }
#pragma unroll
            for (int mt = 0; mt < 2; mt++)
#pragma unroll
                for (int nt = 0; nt < 2; nt++)
                    MMA16816(acc[mt][nt], a[mt], bb[nt]);
        }
    }

    // write partial KV [64][64]
    const int g = lane >> 2, cc = (lane & 3) * 2;
    float* outp = KVp + ((size_t)(sp * 64 + bh)) * (DK * DK);
#pragma unroll
    for (int mt = 0; mt < 2; mt++)
#pragma unroll
        for (int nt = 0; nt < 2; nt++) {
            const int d0 = wm * 32 + mt * 16 + g;
            const int e0 = wn * 16 + nt * 8 + cc;
            float2 p0; p0.x = acc[mt][nt][0]; p0.y = acc[mt][nt][1];
            float2 p1; p1.x = acc[mt][nt][2]; p1.y = acc[mt][nt][3];
            *(float2*)(outp + d0 * DK + e0) = p0;
            *(float2*)(outp + (d0 + 8) * DK + e0) = p1;
        }
    if (tid < 64)
        KSp[((size_t)(sp * 64 + bh)) * DK + tid] = kacc;
}

// ---------------- parallel reduce of KV partials ---------------------------
__global__ void __launch_bounds__(256)
kv_reduce(const float* __restrict__ KVp, const float* __restrict__ KSp,
          float* __restrict__ KV, float* __restrict__ KS)
{
    const int bh = blockIdx.x;
    const int part = blockIdx.y;        // 0..3
    const int tid = threadIdx.x;
    const int e4 = part * 256 + tid;    // float4 index 0..1023

    const float4* src = (const float4*)KVp;
    float4 s; s.x = 0.f; s.y = 0.f; s.z = 0.f; s.w = 0.f;
#pragma unroll
    for (int r = 0; r < KSPL; r++) {
        float4 v = src[((size_t)(r * 64 + bh)) * (DK * DK / 4) + e4];
        s.x += v.x; s.y += v.y; s.z += v.z; s.w += v.w;
    }
    ((float4*)KV)[(size_t)bh * (DK * DK / 4) + e4] = s;

    if (part == 0 && tid < DK) {
        float t = 0.0f;
#pragma unroll
        for (int r = 0; r < KSPL; r++)
            t += KSp[((size_t)(r * 64 + bh)) * DK + tid];
        KS[(size_t)bh * DK + tid] = t;
    }
}

// ---------------- attention normalize: fp16 Q -> fp16 output ---------------
__global__ void __launch_bounds__(256)
attn_kernel(const __half* __restrict__ Q16, const float* __restrict__ KV,
            const float* __restrict__ KS, __half* __restrict__ A16)
{
    const int bh = blockIdx.x;          // 0..63
    const int sc = blockIdx.y;          // 0..7 (512 rows per block)
    const int b = bh >> 4, h = bh & 15;
    const int tid = threadIdx.x;
    const int w = tid >> 5, l = tid & 31;

    __shared__ float KVs[DK * DK];
    __shared__ float KSs[DK];
    __shared__ float qb[8][8][64];      // [warp][row][dk]

    for (int i = tid; i < (DK * DK) / 4; i += 256)
        ((float4*)KVs)[i] = ((const float4*)(KV + (size_t)bh * DK * DK))[i];
    if (tid < DK) KSs[tid] = KS[(size_t)bh * DK + tid];
    __syncthreads();

    const size_t qbase = ((size_t)(b * SS) + sc * 512 + w * 64) * DD + h * DK;

    for (int g = 0; g < 8; g++) {
        const __half* qrow = Q16 + qbase + (size_t)(g * 8) * DD;
#pragma unroll
        for (int t = 0; t < 2; t++) {
            const int idx = l + t * 32;           // 0..63
            const int r = idx >> 3, seg = idx & 7;
            uint4 raw = *(const uint4*)(qrow + (size_t)r * DD + seg * 8);
            const __half2* hp = (const __half2*)&raw;
            float2 f0 = __half22float2(hp[0]);
            float2 f1 = __half22float2(hp[1]);
            float2 f2 = __half22float2(hp[2]);
            float2 f3 = __half22float2(hp[3]);
            float* dst = &qb[w][r][seg * 8];
            float4 o0; o0.x = f0.x; o0.y = f0.y; o0.z = f1.x; o0.w = f1.y;
            float4 o1; o1.x = f2.x; o1.y = f2.y; o1.z = f3.x; o1.w = f3.y;
            *(float4*)(dst)     = o0;
            *(float4*)(dst + 4) = o1;
        }
        __syncwarp();

        float n0[8], n1[8], dn[8];
#pragma unroll
        for (int r = 0; r < 8; r++) { n0[r] = 0.f; n1[r] = 0.f; dn[r] = 0.f; }
#pragma unroll
        for (int dk = 0; dk < DK; dk++) {
            const float kv0 = KVs[dk * DK + l];
            const float kv1 = KVs[dk * DK + l + 32];
            const float ksv = KSs[dk];
#pragma unroll
            for (int r = 0; r < 8; r++) {
                const float q = qb[w][r][dk];
                n0[r] += q * kv0;
                n1[r] += q * kv1;
                dn[r] += q * ksv;
            }
        }
#pragma unroll
        for (int r = 0; r < 8; r++) {
            const size_t orow = qbase + (size_t)(g * 8 + r) * DD;
            const float inv = 1.0f / (dn[r] + 1e-6f);
            A16[orow + l]      = __float2half_rn(n0[r] * inv);
            A16[orow + l + 32] = __float2half_rn(n1[r] * inv);
        }
        __syncwarp();
    }
}

// ---------------- launch ---------------------------------------------------
extern "C" void kernel_launch(void* const* d_in, const int* in_sizes, int n_in,
                              void* d_out, int out_size)
{
    const float* query = (const float*)d_in[0];
    const float* key   = (const float*)d_in[1];
    const float* value = (const float*)d_in[2];
    const float* Wq    = (const float*)d_in[3];
    const float* Wk    = (const float*)d_in[4];
    const float* Wv    = (const float*)d_in[5];
    const float* Wo    = (const float*)d_in[6];
    const float* bo    = (const float*)d_in[7];
    float* out = (float*)d_out;

    float *gKVp, *gKSp, *gKV, *gKS;
    __half *q16, *k16, *v16, *a16, *qo16, *ko16, *vo16;
    __half *wq16, *wk16, *wv16, *wo16;
    cudaGetSymbolAddress((void**)&gKVp, g_KVp);
    cudaGetSymbolAddress((void**)&gKSp, g_KSp);
    cudaGetSymbolAddress((void**)&gKV, g_KV);
    cudaGetSymbolAddress((void**)&gKS, g_KS);
    cudaGetSymbolAddress((void**)&q16, g_q16);
    cudaGetSymbolAddress((void**)&k16, g_k16);
    cudaGetSymbolAddress((void**)&v16, g_v16);
    cudaGetSymbolAddress((void**)&a16, g_a16);
    cudaGetSymbolAddress((void**)&qo16, g_qo16);
    cudaGetSymbolAddress((void**)&ko16, g_ko16);
    cudaGetSymbolAddress((void**)&vo16, g_vo16);
    cudaGetSymbolAddress((void**)&wq16, g_wq16);
    cudaGetSymbolAddress((void**)&wk16, g_wk16);
    cudaGetSymbolAddress((void**)&wv16, g_wv16);
    cudaGetSymbolAddress((void**)&wo16, g_wo16);

    cudaFuncSetAttribute(gemm_mma, cudaFuncAttributeMaxDynamicSharedMemorySize,
                         GSMEM);
    cudaFuncSetAttribute(kv_tc, cudaFuncAttributeMaxDynamicSharedMemorySize,
                         KVSMEM);

    // one-time side stream + events for fork/join (work per call identical)
    static cudaStream_t s1 = nullptr;
    static cudaEvent_t evA = nullptr, evB = nullptr;
    if (s1 == nullptr) {
        cudaStreamCreateWithFlags(&s1, cudaStreamNonBlocking);
        cudaEventCreateWithFlags(&evA, cudaEventDisableTiming);
        cudaEventCreateWithFlags(&evB, cudaEventDisableTiming);
    }

    // single fused conversion launch (3 activations + 4 weights)
    const int nAct4 = (MM * DD) / 4;   // 4194304
    const int nW4   = (DD * DD) / 4;   // 262144
    ConvArgs ca;
    ca.src[0] = query; ca.dst[0] = q16;
    ca.src[1] = key;   ca.dst[1] = k16;
    ca.src[2] = value; ca.dst[2] = v16;
    ca.src[3] = Wq;    ca.dst[3] = wq16;
    ca.src[4] = Wk;    ca.dst[4] = wk16;
    ca.src[5] = Wv;    ca.dst[5] = wv16;
    ca.src[6] = Wo;    ca.dst[6] = wo16;
    ca.start[0] = 0;
    ca.start[1] = nAct4;
    ca.start[2] = 2 * nAct4;
    ca.start[3] = 3 * nAct4;
    ca.start[4] = 3 * nAct4 + nW4;
    ca.start[5] = 3 * nAct4 + 2 * nW4;
    ca.start[6] = 3 * nAct4 + 3 * nW4;
    ca.start[7] = 3 * nAct4 + 4 * nW4;
    conv_all<<<(ca.start[7] + 255) / 256, 256>>>(ca);

    // fork: Q projection on side stream, K/V projections + kv chain on main
    cudaEventRecord(evA, 0);
    cudaStreamWaitEvent(s1, evA, 0);

    GemmArgs aQ;
    aQ.A[0] = q16; aQ.B[0] = wq16; aQ.C[0] = qo16; aQ.bias[0] = bo; aQ.mode[0] = 3;
    aQ.A[1] = q16; aQ.B[1] = wq16; aQ.C[1] = qo16; aQ.bias[1] = bo; aQ.mode[1] = 3;
    aQ.A[2] = q16; aQ.B[2] = wq16; aQ.C[2] = qo16; aQ.bias[2] = bo; aQ.mode[2] = 3;
    gemm_mma<<<dim3(DD / TN, MM / TM, 1), 256, GSMEM, s1>>>(aQ);
    cudaEventRecord(evB, s1);

    GemmArgs aKV;
    aKV.A[0] = k16; aKV.B[0] = wk16; aKV.C[0] = ko16; aKV.bias[0] = bo; aKV.mode[0] = 3;
    aKV.A[1] = v16; aKV.B[1] = wv16; aKV.C[1] = vo16; aKV.bias[1] = bo; aKV.mode[1] = 4;
    aKV.A[2] = k16; aKV.B[2] = wk16; aKV.C[2] = ko16; aKV.bias[2] = bo; aKV.mode[2] = 3;
    gemm_mma<<<dim3(DD / TN, MM / TM, 2), 256, GSMEM>>>(aKV);

    kv_tc<<<dim3(64, KSPL), 256, KVSMEM>>>(ko16, vo16, gKVp, gKSp);
    kv_reduce<<<dim3(64, 4), 256>>>(gKVp, gKSp, gKV, gKS);

    // join: attn needs Q projection + reduced KV
    cudaStreamWaitEvent(0, evB, 0);
    attn_kernel<<<dim3(64, 8), 256>>>(qo16, gKV, gKS, a16);

    // output projection (+bias)
    GemmArgs ao;
    ao.A[0] = a16; ao.B[0] = wo16; ao.C[0] = out; ao.bias[0] = bo; ao.mode[0] = 2;
    ao.A[1] = a16; ao.B[1] = wo16; ao.C[1] = out; ao.bias[1] = bo; ao.mode[1] = 2;
    ao.A[2] = a16; ao.B[2] = wo16; ao.C[2] = out; ao.bias[2] = bo; ao.mode[2] = 2;
    gemm_mma<<<dim3(DD / TN, MM / TM, 1), 256, GSMEM>>>(ao);
}